// round 10
// baseline (speedup 1.0000x reference)
#include <cuda_runtime.h>
#include <cuda_fp16.h>
#include <cstdint>

#define Bc      32
#define Lc      32768
#define Mc      32
#define Dc      128
#define Pc      4095
#define TILE_P  128
#define NCH     16          // K chunks of 32 (one time-row each)
#define BUFB    16384       // A(8K) + B(8K)
#define SMEM_TOTAL (2 * BUFB)

// weights as fp16, layout [d][k*32+m] (K-contiguous, matches x slab)
__device__ __align__(16) __half g_Bh[Dc * 512];

__global__ void prep_b(const float* __restrict__ w) {
    int idx = blockIdx.x * 256 + threadIdx.x;
    if (idx >= Dc * 512) return;
    int d = idx >> 9, t = idx & 511;
    int k = t >> 5, m = t & 31;
    g_Bh[idx] = __float2half_rn(w[d * 512 + m * 16 + k]);
}

#define LDSM4(f, a)                                                           \
    asm volatile("ldmatrix.sync.aligned.m8n8.x4.shared.b16 {%0,%1,%2,%3},[%4];" \
        : "=r"((f)[0]), "=r"((f)[1]), "=r"((f)[2]), "=r"((f)[3]) : "r"(a))

#define MMA(c4, a, b0, b1)                                                    \
    asm volatile("mma.sync.aligned.m16n8k16.row.col.f32.f16.f16.f32 "         \
        "{%0,%1,%2,%3},{%4,%5,%6,%7},{%8,%9},{%0,%1,%2,%3};"                  \
        : "+f"((c4)[0]), "+f"((c4)[1]), "+f"((c4)[2]), "+f"((c4)[3])          \
        : "r"((a)[0]), "r"((a)[1]), "r"((a)[2]), "r"((a)[3]), "r"(b0), "r"(b1))

#define CP_ASYNC16(dst, src)                                                  \
    asm volatile("cp.async.cg.shared.global [%0], [%1], 16;" :: "r"(dst), "l"(src))
#define CP_COMMIT()  asm volatile("cp.async.commit_group;" ::: "memory")
#define CP_WAIT0()   asm volatile("cp.async.wait_group 0;" ::: "memory")

__device__ __forceinline__ uint32_t h2u(__half2 v) { return *reinterpret_cast<uint32_t*>(&v); }

__global__ __launch_bounds__(128, 2) void patch_encoder_mma(
    const float* __restrict__ x, const float* __restrict__ ts,
    const float* __restrict__ cb, float* __restrict__ out)
{
    extern __shared__ char smc[];
    uint32_t sbase;
    asm("{ .reg .u64 t; cvta.to.shared.u64 t, %1; cvt.u32.u64 %0, t; }"
        : "=r"(sbase) : "l"(smc));

    const int tid  = threadIdx.x;
    const int lane = tid & 31;
    const int wid  = tid >> 5;     // 0..3
    const int wp   = wid >> 1;     // 0..1 : p-tile of 64
    const int wdn  = wid & 1;      // 0..1 : d-tile of 64
    const int b    = blockIdx.y;
    const int p0   = blockIdx.x * TILE_P;

    // ---- staging: thread handles full row tid (0..127): 32 floats of x, 64B of B ----
    int gpc = p0 + tid; if (gpc > Pc - 1) gpc = Pc - 1;          // clamp (row discarded)
    const float* xsrc = x + ((size_t)b * Lc + (size_t)gpc * 8) * Mc;   // + c*Mc per chunk
    const char*  bsrc = (const char*)g_Bh + tid * 1024;                // + c*64 per chunk
    // swizzled smem offsets for this thread's four 16B units (row tid, 64B rows)
    uint32_t so[4];
    #pragma unroll
    for (int j = 0; j < 4; ++j)
        so[j] = tid * 64 + ((j * 16) ^ ((tid * 8) & 0x30));

    float4 av[8];

    auto LDGx = [&](int c) {
        const float4* p = reinterpret_cast<const float4*>(xsrc + (size_t)c * Mc);
        #pragma unroll
        for (int j = 0; j < 8; ++j) av[j] = p[j];
    };
    auto STSa = [&](int bi) {
        char* base = smc + bi * BUFB;
        #pragma unroll
        for (int j = 0; j < 4; ++j) {
            uint4 h;
            h.x = h2u(__floats2half2_rn(av[2*j].x,   av[2*j].y));
            h.y = h2u(__floats2half2_rn(av[2*j].z,   av[2*j].w));
            h.z = h2u(__floats2half2_rn(av[2*j+1].x, av[2*j+1].y));
            h.w = h2u(__floats2half2_rn(av[2*j+1].z, av[2*j+1].w));
            *reinterpret_cast<uint4*>(base + so[j]) = h;
        }
    };
    auto CPb = [&](int c, int bi) {
        uint32_t dst = sbase + bi * BUFB + 8192;
        const char* s = bsrc + c * 64;
        #pragma unroll
        for (int j = 0; j < 4; ++j)
            CP_ASYNC16(dst + so[j], s + j * 16);
        CP_COMMIT();
    };

    // ---- ldmatrix per-lane address components ----
    const uint32_t lrow   = lane & 15;
    const uint32_t colsel = (lane >> 4) * 16;       // bytes
    const uint32_t msk    = (lrow * 8) & 0x30;      // swizzle mask (row-dependent)
    const uint32_t aRow0  = (wp * 64 + lrow) * 64;  // + mt*16*64
    const uint32_t bRow0  = (wdn * 64 + lrow) * 64; // + nt*16*64

    float acc[4][8][4];                             // [mt][n8][quad] = 128 regs
    #pragma unroll
    for (int mt = 0; mt < 4; ++mt)
        #pragma unroll
        for (int j = 0; j < 8; ++j)
            #pragma unroll
            for (int e = 0; e < 4; ++e) acc[mt][j][e] = 0.f;

    auto MATH = [&](int bi) {
        uint32_t base = sbase + bi * BUFB;
        #pragma unroll
        for (int k = 0; k < 2; ++k) {
            uint32_t coff = (k * 32 + colsel) ^ msk;
            uint32_t ah[4][4];
            #pragma unroll
            for (int mt = 0; mt < 4; ++mt)
                LDSM4(ah[mt], base + aRow0 + mt * 1024 + coff);
            #pragma unroll
            for (int nt = 0; nt < 4; ++nt) {
                uint32_t bh[4];
                LDSM4(bh, base + 8192 + bRow0 + nt * 1024 + coff);
                #pragma unroll
                for (int mt = 0; mt < 4; ++mt) {
                    MMA(acc[mt][nt * 2],     ah[mt], bh[0], bh[2]);
                    MMA(acc[mt][nt * 2 + 1], ah[mt], bh[1], bh[3]);
                }
            }
        }
    };

    // ---- pipelined main loop: ONE barrier per chunk (hazards as in R9) ----
    LDGx(0); CPb(0, 0);
    for (int c = 0; c < NCH; ++c) {
        STSa(c & 1);
        CP_WAIT0();
        __syncthreads();
        if (c + 1 < NCH) {
            LDGx(c + 1);
            CPb(c + 1, (c + 1) & 1);
        }
        MATH(c & 1);
    }

    // ---- epilogue: bias + sinusoidal PE (median == ts[p*8+7]; windows pre-sorted) ----
    const int tq = lane >> 2, tr = lane & 3;
    const float CC = -0.0719557839f;        // -ln(10000)/128

    float fr[8]; float2 bb[8];
    #pragma unroll
    for (int j = 0; j < 8; ++j) {
        int c = wdn * 64 + j * 8 + tr * 2;
        fr[j] = expf((float)c * CC);
        bb[j] = *reinterpret_cast<const float2*>(cb + c);
    }

    #pragma unroll
    for (int mt = 0; mt < 4; ++mt) {
        const int gp1 = p0 + wp * 64 + mt * 16 + tq;
        const int gp2 = gp1 + 8;
        const float med1 = ts[(size_t)b * Lc + gp1 * 8 + 7];
        const float med2 = ts[(size_t)b * Lc + gp2 * 8 + 7];
        const bool v1 = gp1 < Pc, v2 = gp2 < Pc;
        float* o1 = out + ((size_t)b * Pc + gp1) * Dc;
        float* o2 = out + ((size_t)b * Pc + gp2) * Dc;
        #pragma unroll
        for (int j = 0; j < 8; ++j) {
            int c = wdn * 64 + j * 8 + tr * 2;
            float s, co;
            sincosf(med1 * fr[j], &s, &co);
            if (v1) {
                float2 r1 = { acc[mt][j][0] + bb[j].x + s, acc[mt][j][1] + bb[j].y + co };
                *reinterpret_cast<float2*>(o1 + c) = r1;
            }
            sincosf(med2 * fr[j], &s, &co);
            if (v2) {
                float2 r2 = { acc[mt][j][2] + bb[j].x + s, acc[mt][j][3] + bb[j].y + co };
                *reinterpret_cast<float2*>(o2 + c) = r2;
            }
        }
    }
}

extern "C" void kernel_launch(void* const* d_in, const int* in_sizes, int n_in,
                              void* d_out, int out_size) {
    const float* x  = (const float*)d_in[0];   // [B, L, M]
    const float* ts = (const float*)d_in[1];   // [B, L]
    const float* w  = (const float*)d_in[2];   // [D, M, K]
    const float* cb = (const float*)d_in[3];   // [D]
    float* out = (float*)d_out;                // [B, P, D]

    cudaFuncSetAttribute(patch_encoder_mma,
                         cudaFuncAttributeMaxDynamicSharedMemorySize, SMEM_TOTAL);

    prep_b<<<(Dc * 512 + 255) / 256, 256>>>(w);

    dim3 grid((Pc + TILE_P - 1) / TILE_P, Bc);   // (32, 32)
    patch_encoder_mma<<<grid, 128, SMEM_TOTAL>>>(x, ts, cb, out);
}

// round 12
// speedup vs baseline: 1.3554x; 1.3554x over previous
#include <cuda_runtime.h>
#include <cuda_fp16.h>
#include <cstdint>

#define Bc      32
#define Lc      32768
#define Mc      32
#define Dc      128
#define Pc      4095
#define TILE_P  128
#define NCH     16          // K chunks of 32 (one time-row each)
#define BUFB    16384       // A(8K) + B(8K)
#define NSTAGE  3
#define SMEM_TOTAL (NSTAGE * BUFB)

// weights as fp16, layout [d][k*32+m] (K-contiguous, matches x slab)
__device__ __align__(16) __half g_Bh[Dc * 512];

__global__ void prep_b(const float* __restrict__ w) {
    int idx = blockIdx.x * 256 + threadIdx.x;
    if (idx >= Dc * 512) return;
    int d = idx >> 9, t = idx & 511;
    int k = t >> 5, m = t & 31;
    g_Bh[idx] = __float2half_rn(w[d * 512 + m * 16 + k]);
}

#define LDSM4(f, a)                                                           \
    asm volatile("ldmatrix.sync.aligned.m8n8.x4.shared.b16 {%0,%1,%2,%3},[%4];" \
        : "=r"((f)[0]), "=r"((f)[1]), "=r"((f)[2]), "=r"((f)[3]) : "r"(a))

#define MMA(c4, a, b0, b1)                                                    \
    asm volatile("mma.sync.aligned.m16n8k16.row.col.f32.f16.f16.f32 "         \
        "{%0,%1,%2,%3},{%4,%5,%6,%7},{%8,%9},{%0,%1,%2,%3};"                  \
        : "+f"((c4)[0]), "+f"((c4)[1]), "+f"((c4)[2]), "+f"((c4)[3])          \
        : "r"((a)[0]), "r"((a)[1]), "r"((a)[2]), "r"((a)[3]), "r"(b0), "r"(b1))

#define CP_ASYNC16(dst, src)                                                  \
    asm volatile("cp.async.cg.shared.global [%0], [%1], 16;" :: "r"(dst), "l"(src))
#define CP_COMMIT()  asm volatile("cp.async.commit_group;" ::: "memory")
#define CP_WAIT1()   asm volatile("cp.async.wait_group 1;" ::: "memory")
#define CP_WAIT0()   asm volatile("cp.async.wait_group 0;" ::: "memory")

__device__ __forceinline__ uint32_t h2u(__half2 v) { return *reinterpret_cast<uint32_t*>(&v); }

__global__ __launch_bounds__(256, 2) void patch_encoder_mma(
    const float* __restrict__ x, const float* __restrict__ ts,
    const float* __restrict__ cb, float* __restrict__ out)
{
    extern __shared__ char smc[];
    uint32_t sbase;
    asm("{ .reg .u64 t; cvta.to.shared.u64 t, %1; cvt.u32.u64 %0, t; }"
        : "=r"(sbase) : "l"(smc));

    const int tid  = threadIdx.x;
    const int lane = tid & 31;
    const int wid  = tid >> 5;
    const int wp   = wid >> 1;     // 0..3 : p-tile of 32
    const int wdn  = wid & 1;      // 0..1 : d-tile of 64
    const int b    = blockIdx.y;
    const int p0   = blockIdx.x * TILE_P;

    // ---- staging indices: thread handles row sr (0..127), half sq (16 elems) ----
    const int sr = tid >> 1, sq = tid & 1;
    int gpc = p0 + sr; if (gpc > Pc - 1) gpc = Pc - 1;           // clamp (rows discarded)
    const float* xsrc = x + ((size_t)b * Lc + (size_t)gpc * 8) * Mc + sq * 16;
    // swizzled smem offsets for this thread's two 16B units (row sr, 64B rows)
    const uint32_t so0 = sr * 64 + ((sq * 32)      ^ ((sr * 8) & 0x30));
    const uint32_t so1 = sr * 64 + ((sq * 32 + 16) ^ ((sr * 8) & 0x30));
    const char* bsrc = (const char*)g_Bh + sr * 1024 + sq * 32;  // + c*64 per chunk

    float4 av0, av1, av2, av3;

    auto LDGx = [&](int c) {
        const float4* p = reinterpret_cast<const float4*>(xsrc + (size_t)c * Mc);
        av0 = p[0]; av1 = p[1]; av2 = p[2]; av3 = p[3];
    };
    auto STSa = [&](int bi) {
        char* base = smc + bi * BUFB;
        uint4 h0, h1;
        h0.x = h2u(__floats2half2_rn(av0.x, av0.y));
        h0.y = h2u(__floats2half2_rn(av0.z, av0.w));
        h0.z = h2u(__floats2half2_rn(av1.x, av1.y));
        h0.w = h2u(__floats2half2_rn(av1.z, av1.w));
        h1.x = h2u(__floats2half2_rn(av2.x, av2.y));
        h1.y = h2u(__floats2half2_rn(av2.z, av2.w));
        h1.z = h2u(__floats2half2_rn(av3.x, av3.y));
        h1.w = h2u(__floats2half2_rn(av3.z, av3.w));
        *reinterpret_cast<uint4*>(base + so0) = h0;
        *reinterpret_cast<uint4*>(base + so1) = h1;
    };
    auto CPb = [&](int c, int bi) {
        uint32_t dst = sbase + bi * BUFB + 8192;
        const char* s = bsrc + c * 64;
        CP_ASYNC16(dst + so0, s);
        CP_ASYNC16(dst + so1, s + 16);
        CP_COMMIT();
    };

    // ---- ldmatrix per-lane address components ----
    const uint32_t lrow   = lane & 15;
    const uint32_t colsel = (lane >> 4) * 16;       // bytes
    const uint32_t msk    = (lrow * 8) & 0x30;      // swizzle mask (row-dependent)
    const uint32_t aRow0  = (wp * 32 + lrow) * 64;  // m-tile 0 (+16*64 for m-tile 1)
    const uint32_t bRow0  = (wdn * 64 + lrow) * 64;

    float acc[2][8][4];
    #pragma unroll
    for (int mt = 0; mt < 2; ++mt)
        #pragma unroll
        for (int j = 0; j < 8; ++j)
            #pragma unroll
            for (int e = 0; e < 4; ++e) acc[mt][j][e] = 0.f;

    auto MATH = [&](int bi) {
        uint32_t base = sbase + bi * BUFB;
        #pragma unroll
        for (int k = 0; k < 2; ++k) {
            uint32_t coff = (k * 32 + colsel) ^ msk;
            uint32_t ah[2][4];
            LDSM4(ah[0], base + aRow0 + coff);
            LDSM4(ah[1], base + aRow0 + 1024 + coff);    // +16 rows
            #pragma unroll
            for (int nt = 0; nt < 4; ++nt) {
                uint32_t bh[4];
                LDSM4(bh, base + 8192 + bRow0 + nt * 1024 + coff);
                #pragma unroll
                for (int mt = 0; mt < 2; ++mt) {
                    MMA(acc[mt][nt * 2],     ah[mt], bh[0], bh[2]);
                    MMA(acc[mt][nt * 2 + 1], ah[mt], bh[1], bh[3]);
                }
            }
        }
    };

    // ---- 3-stage pipelined main loop, ONE barrier per chunk ----
    // iter c: STSa(c+1) [av from iter c-1 -> full-iter LDG slack]; CPb(c+1);
    //         wait_group 1 (group c, issued a full iter ago); barrier;
    //         LDGx(c+2); MATH(c)
    // Hazards (3 buffers): writer at iter c hits buf (c+1)%3; its previous
    // reader MATH(c-2) precedes barrier(c-1) in program order; writer follows
    // barrier(c-1) -> safe. Same argument for cp.async B.
    LDGx(0);
    STSa(0); CPb(0, 0);            // stage chunk 0 into buffer 0
    LDGx(1);                       // av = chunk 1 for iter 0's STSa

    int bm = 0, bs = 1;            // buffer for MATH(c) / for staging chunk c+1
    for (int c = 0; c < NCH; ++c) {
        if (c + 1 < NCH) {
            STSa(bs);
            CPb(c + 1, bs);
            CP_WAIT1();
        } else {
            CP_WAIT0();
        }
        __syncthreads();
        if (c + 2 < NCH) LDGx(c + 2);
        MATH(bm);
        bm = bs;
        bs = (bs == NSTAGE - 1) ? 0 : bs + 1;
    }

    // ---- epilogue: bias + sinusoidal PE (median == ts[p*8+7]; windows pre-sorted) ----
    const int tq = lane >> 2, tr = lane & 3;
    const float CC = -0.0719557839f;        // -ln(10000)/128

    float fr[8]; float2 bb[8];
    #pragma unroll
    for (int j = 0; j < 8; ++j) {
        int c = wdn * 64 + j * 8 + tr * 2;
        fr[j] = expf((float)c * CC);
        bb[j] = *reinterpret_cast<const float2*>(cb + c);
    }

    #pragma unroll
    for (int mt = 0; mt < 2; ++mt) {
        const int gp1 = p0 + wp * 32 + mt * 16 + tq;
        const int gp2 = gp1 + 8;
        const float med1 = ts[(size_t)b * Lc + gp1 * 8 + 7];
        const float med2 = ts[(size_t)b * Lc + gp2 * 8 + 7];
        const bool v1 = gp1 < Pc, v2 = gp2 < Pc;
        float* o1 = out + ((size_t)b * Pc + gp1) * Dc;
        float* o2 = out + ((size_t)b * Pc + gp2) * Dc;
        #pragma unroll
        for (int j = 0; j < 8; ++j) {
            int c = wdn * 64 + j * 8 + tr * 2;
            float s, co;
            sincosf(med1 * fr[j], &s, &co);
            if (v1) {
                float2 r1 = { acc[mt][j][0] + bb[j].x + s, acc[mt][j][1] + bb[j].y + co };
                *reinterpret_cast<float2*>(o1 + c) = r1;
            }
            sincosf(med2 * fr[j], &s, &co);
            if (v2) {
                float2 r2 = { acc[mt][j][2] + bb[j].x + s, acc[mt][j][3] + bb[j].y + co };
                *reinterpret_cast<float2*>(o2 + c) = r2;
            }
        }
    }
}

extern "C" void kernel_launch(void* const* d_in, const int* in_sizes, int n_in,
                              void* d_out, int out_size) {
    const float* x  = (const float*)d_in[0];   // [B, L, M]
    const float* ts = (const float*)d_in[1];   // [B, L]
    const float* w  = (const float*)d_in[2];   // [D, M, K]
    const float* cb = (const float*)d_in[3];   // [D]
    float* out = (float*)d_out;                // [B, P, D]

    cudaFuncSetAttribute(patch_encoder_mma,
                         cudaFuncAttributeMaxDynamicSharedMemorySize, SMEM_TOTAL);

    prep_b<<<(Dc * 512 + 255) / 256, 256>>>(w);

    dim3 grid((Pc + TILE_P - 1) / TILE_P, Bc);   // (32, 32)
    patch_encoder_mma<<<grid, 256, SMEM_TOTAL>>>(x, ts, cb, out);
}